// round 3
// baseline (speedup 1.0000x reference)
#include <cuda_runtime.h>
#include <cstddef>

#define B_      128
#define NNZ_    128
#define H_      128
#define KOUT_   4096
#define FDIM_   135909

// Intermediate val1 [B, H] — device global scratch (no allocations allowed).
__device__ float g_val1[B_ * H_];

// ---------------------------------------------------------------------------
// Layer 1: val1[b,h] = relu( sum_i v[b,i] * W1[h, fidx[b,i]] + b1[h] )
// Warp per (b,h): each lane gathers 4 W1 elements (independent -> MLP=4/lane),
// then a 5-stage butterfly reduce. Block = 8 warps = 8 h's of one b; indices
// and values for that b staged once in smem. Grid = 128 b * 16 = 2048 blocks
// (vs 128 before) -> ~16x more concurrent warps feeding the DRAM queues.
// ---------------------------------------------------------------------------
__global__ __launch_bounds__(256) void layer1_kernel(
    const float* __restrict__ inv,
    const int*   __restrict__ fidx,
    const float* __restrict__ W1,
    const float* __restrict__ b1)
{
    const int tid  = threadIdx.x;
    const int warp = tid >> 5;
    const int lane = tid & 31;
    const int b    = blockIdx.x >> 4;
    const int h    = ((blockIdx.x & 15) << 3) + warp;

    __shared__ int   sidx[NNZ_];
    __shared__ float sval[NNZ_];
    if (tid < 128) sidx[tid]       = fidx[(b << 7) + tid];
    else           sval[tid - 128] = inv [(b << 7) + tid - 128];
    __syncthreads();

    const float* w = W1 + (size_t)h * FDIM_;
    const int4   i4 = reinterpret_cast<const int4*>(sidx)[lane];
    const float4 v4 = reinterpret_cast<const float4*>(sval)[lane];

    const float w0 = __ldg(w + i4.x);
    const float w1 = __ldg(w + i4.y);
    const float w2 = __ldg(w + i4.z);
    const float w3 = __ldg(w + i4.w);

    float acc = w0 * v4.x + w1 * v4.y + w2 * v4.z + w3 * v4.w;

    #pragma unroll
    for (int o = 16; o > 0; o >>= 1)
        acc += __shfl_xor_sync(0xffffffffu, acc, o);

    if (lane == 0)
        g_val1[(b << 7) + h] = fmaxf(acc + __ldg(b1 + h), 0.0f);
}

// ---------------------------------------------------------------------------
// Layer 2: val2[b,k] = <val1[b,:], W2[lab[b,k],:]> + b2[lab[b,k]]
// One warp handles 8 outputs: 8 independent coalesced float4 row-loads per
// lane are issued back-to-back (MLP=8) before any FMA. Block = 256 thr =
// 8 warps = 64 outputs of one batch row b; val1[b] staged once in smem.
// Grid = (B*KOUT)/64 = 8192 blocks.
// ---------------------------------------------------------------------------
__global__ __launch_bounds__(256) void layer2_kernel(
    const int*   __restrict__ lab,
    const float* __restrict__ W2,
    const float* __restrict__ b2,
    float*       __restrict__ out,
    float*       __restrict__ out_lab)   // may be null
{
    const int warp  = threadIdx.x >> 5;
    const int lane  = threadIdx.x & 31;
    const int b     = blockIdx.x >> 6;                      // 64 blocks per b
    const int kbase = ((blockIdx.x & 63) << 6) + (warp << 3);

    __shared__ float4 s4[32];
    if (threadIdx.x < 32)
        s4[threadIdx.x] = reinterpret_cast<const float4*>(g_val1 + (b << 7))[threadIdx.x];
    __syncthreads();

    const float4 sv = s4[lane];
    const int base = (b << 12) + kbase;

    int rows[8];
    #pragma unroll
    for (int j = 0; j < 8; j++) rows[j] = lab[base + j];

    float4 wv[8];
    #pragma unroll
    for (int j = 0; j < 8; j++)
        wv[j] = __ldg(reinterpret_cast<const float4*>(W2) +
                      ((size_t)rows[j] << 5) + lane);

    float acc[8];
    #pragma unroll
    for (int j = 0; j < 8; j++)
        acc[j] = wv[j].x * sv.x + wv[j].y * sv.y + wv[j].z * sv.z + wv[j].w * sv.w;

    #pragma unroll
    for (int j = 0; j < 8; j++) {
        #pragma unroll
        for (int o = 16; o > 0; o >>= 1)
            acc[j] += __shfl_xor_sync(0xffffffffu, acc[j], o);
    }

    if (lane < 8) {
        const int r = rows[lane];
        out[base + lane] = acc[lane] + __ldg(b2 + r);
        if (out_lab) out_lab[base + lane] = (float)r;
    }
}

// ---------------------------------------------------------------------------
extern "C" void kernel_launch(void* const* d_in, const int* in_sizes, int n_in,
                              void* d_out, int out_size)
{
    const float* inv  = (const float*)d_in[0];   // in_values        [B, NNZ]
    const int*   fidx = (const int*)  d_in[1];   // active_in_indices[B, NNZ]
    const int*   lab  = (const int*)  d_in[2];   // active_label_idx [B, KOUT]
    const float* W1   = (const float*)d_in[3];   // [H, FDIM]
    const float* b1   = (const float*)d_in[4];   // [H]
    const float* W2   = (const float*)d_in[5];   // [C, H]
    const float* b2   = (const float*)d_in[6];   // [C]

    float* out = (float*)d_out;
    const int n_val2 = B_ * KOUT_;
    float* out_lab = (out_size >= 2 * n_val2) ? (out + n_val2) : nullptr;

    layer1_kernel<<<(B_ * 16), 256>>>(inv, fidx, W1, b1);
    layer2_kernel<<<(B_ * KOUT_) / 64, 256>>>(lab, W2, b2, out, out_lab);
}